// round 15
// baseline (speedup 1.0000x reference)
#include <cuda_runtime.h>

// out[b, j1*64 + j2] = x[b, 0, j1] * x[b, 1, j2]
// x: [32768, 2, 64] f32, out: [32768, 4096] f32
// 1 batch row per CTA (finest granularity: 32768 independent CTAs for max
// cross-CTA store MLP); 256 threads; each thread writes 4x float4 via
// streaming (evict-first) STG.128 stores.

#define N_MF    64
#define ROW_IN  128   // 2 * 64 floats per batch row
#define ROW_OUT 4096

__global__ void __launch_bounds__(256, 8)
anfis_outer_kernel(const float* __restrict__ x, float* __restrict__ out) {
    const int b   = blockIdx.x;
    const int tid = threadIdx.x;

    __shared__ float sa[N_MF];   // x[b, 0, :]
    __shared__ float sb[N_MF];   // x[b, 1, :]

    const float* __restrict__ xb = x + (size_t)b * ROW_IN;
    if (tid < ROW_IN) {
        float v = __ldg(xb + tid);
        if (tid < N_MF) sa[tid] = v;
        else            sb[tid - N_MF] = v;
    }
    __syncthreads();

    float4* __restrict__ o4 = reinterpret_cast<float4*>(out + (size_t)b * ROW_OUT);

    #pragma unroll
    for (int k = 0; k < 4; ++k) {
        const int idx = k * 1024 + tid * 4;       // linear output index
        const int j1  = idx >> 6;                 // 0..63
        const int j2  = idx & 63;                 // multiple of 4
        const float  av = sa[j1];
        const float4 bv = *reinterpret_cast<const float4*>(&sb[j2]);
        float4 v;
        v.x = av * bv.x;
        v.y = av * bv.y;
        v.z = av * bv.z;
        v.w = av * bv.w;
        __stcs(&o4[idx >> 2], v);                 // streaming: evict-first in L2
    }
}

extern "C" void kernel_launch(void* const* d_in, const int* in_sizes, int n_in,
                              void* d_out, int out_size) {
    const float* x = (const float*)d_in[0];
    float* out = (float*)d_out;
    const int batch = in_sizes[0] / ROW_IN;   // 32768
    anfis_outer_kernel<<<batch, 256>>>(x, out);
}